// round 14
// baseline (speedup 1.0000x reference)
#include <cuda_runtime.h>
#include <cstdint>
#include <math.h>

#define BB      32
#define PP      10208
#define PP_PAD  10240
#define CC      81
#define FG      80
#define PRE_K   400
#define MAXDET  100
#define SELCAP  2048
#define KEYCAP  4096
#define NBINS   4096
#define CONF    0.01f
#define NMST    0.45f
#define Wf      1280.0f
#define Hf      1024.0f
#define OFFC    1281.0f
#define G       8
#define NW      13

// ---------------- global scratch (zero-initialized device globals) ---------
__device__ float              g_pmax[BB * PP];
__device__ unsigned           g_hist[BB * NBINS];  // kTau re-zeros after use
__device__ unsigned long long g_keys[BB * KEYCAP];
__device__ int                g_cnt[BB];           // kC re-zeros after use
__device__ int                g_selidx[BB * SELCAP];  // overwritten each run
__device__ int                g_selcnt[BB];           // overwritten each run
__device__ int                g_tau[BB * 2];          // overwritten each run

// order-preserving float<->uint maps
__device__ __forceinline__ unsigned f2ord(float f) {
    unsigned u = __float_as_uint(f);
    return (u & 0x80000000u) ? ~u : (u | 0x80000000u);
}
__device__ __forceinline__ float ord2f(unsigned v) {
    unsigned u = (v & 0x80000000u) ? (v ^ 0x80000000u) : ~v;
    return __uint_as_float(u);
}

// -- K1: per-prior max fg score = 1/sum(exp(xi-mf)); 8 rows/warp, MLP=24.
//    launch_bounds(256,4) -> 64 regs so the 24-load batch stays in registers --
__global__ void __launch_bounds__(256, 4) k1_priormax(const float* __restrict__ logits) {
    int wid  = (blockIdx.x * blockDim.x + threadIdx.x) >> 5;
    int lane = threadIdx.x & 31;
    int row  = wid * G;
    if (row >= BB * PP) return;
    const float* p = logits + (size_t)row * CC;
    float a0[G], a1[G], a2[G];
#pragma unroll
    for (int g = 0; g < G; g++) {
        a0[g] = __ldg(p + g * CC + lane);
        a1[g] = __ldg(p + g * CC + 32 + lane);
        a2[g] = (lane < 17) ? __ldg(p + g * CC + 64 + lane) : -3.0e38f;
    }
    float keep = 0.0f;
#pragma unroll
    for (int g = 0; g < G; g++) {
        float xf = fmaxf((lane == 0) ? -3.0e38f : a0[g], fmaxf(a1[g], a2[g]));
        float mf = ord2f(__reduce_max_sync(0xffffffffu, f2ord(xf)));
        float s = __expf(a0[g] - mf) + __expf(a1[g] - mf) +
                  ((lane < 17) ? __expf(a2[g] - mf) : 0.0f);
#pragma unroll
        for (int o = 16; o; o >>= 1) s += __shfl_xor_sync(0xffffffffu, s, o);
        float r = __fdividef(1.0f, s);
        if (lane == g) keep = r;
    }
    if (lane < G) {
        g_pmax[row + lane] = keep;
        int b = row / PP;
        atomicAdd(&g_hist[b * NBINS + (__float_as_uint(keep) >> 18)], 1u);
    }
}

// boundary: largest bin Bb with count(bins >= Bb) >= T; *s_above = strictly above
// (requires 1024-thread block)
__device__ __forceinline__ int boundary(const unsigned* __restrict__ h, int T,
                                        int* s_minR, unsigned* s_above,
                                        unsigned* s_wsum) {
    int t = threadIdx.x, lane = t & 31, w = t >> 5;
    __syncthreads();
    if (t == 0) { *s_minR = 0x7fffffff; *s_above = 0u; }
    __syncthreads();
    int base = 4095 - 4 * t;
    unsigned c0 = h[base], c1 = h[base - 1], c2 = h[base - 2], c3 = h[base - 3];
    unsigned part = c0 + c1 + c2 + c3;
    unsigned v = part;
#pragma unroll
    for (int o = 1; o < 32; o <<= 1) {
        unsigned u = __shfl_up_sync(0xffffffffu, v, o);
        if (lane >= o) v += u;
    }
    if (lane == 31) s_wsum[w] = v;
    __syncthreads();
    if (w == 0) {
        unsigned x = s_wsum[lane];
#pragma unroll
        for (int o = 1; o < 32; o <<= 1) {
            unsigned u = __shfl_up_sync(0xffffffffu, x, o);
            if (lane >= o) x += u;
        }
        s_wsum[lane] = x;
    }
    __syncthreads();
    unsigned excl = ((w > 0) ? s_wsum[w - 1] : 0u) + (v - part);
    unsigned cum = excl, myAbove = 0;
    int myR = 0x7fffffff;
    unsigned cs[4] = {c0, c1, c2, c3};
#pragma unroll
    for (int i2 = 0; i2 < 4; i2++) {
        unsigned prev = cum;
        cum += cs[i2];
        if (myR == 0x7fffffff && cum >= (unsigned)T) { myR = 4 * t + i2; myAbove = prev; }
    }
    if (myR != 0x7fffffff) atomicMin(s_minR, myR);
    __syncthreads();
    int r = *s_minR;
    if (r == myR && myR != 0x7fffffff) *s_above = myAbove;
    __syncthreads();
    return (r == 0x7fffffff) ? 0 : (4095 - r);
}

// ---- kTau: one block per batch; computes tau + prior selection once ----
__global__ void __launch_bounds__(1024) kTau() {
    __shared__ unsigned hist[NBINS];
    __shared__ unsigned s_wsum[32];
    __shared__ int s_minR, s_cnt;
    __shared__ unsigned s_above;
    int b = blockIdx.x, t = threadIdx.x, lane = t & 31;
    unsigned lt = (1u << lane) - 1u;
    const float* pmaxb = g_pmax + b * PP;

    if (t == 0) s_cnt = 0;
    for (int i = t; i < NBINS; i += 1024) {
        unsigned* gh = &g_hist[b * NBINS + i];
        hist[i] = *gh;
        *gh = 0u;                      // replay re-zero (same thread reads+zeros)
    }
    int BbA = boundary(hist, PRE_K, &s_minR, &s_above, s_wsum);
    int needA = PRE_K - (int)s_above;
    for (int i = t; i < NBINS; i += 1024) hist[i] = 0u;
    __syncthreads();
    for (int i = t; i < PP; i += 1024) {
        unsigned bits = __float_as_uint(pmaxb[i]);
        if ((int)(bits >> 18) == BbA) atomicAdd(&hist[(bits >> 6) & 0xFFF], 1u);
    }
    int Bb2A = boundary(hist, needA, &s_minR, &s_above, s_wsum);
    if (Bb2A > 0) Bb2A--;              // one fine-bin slack (covers k1 __expf noise)

    // select priors with pmax >= tau into global list
    for (int i0 = 0; i0 < PP_PAD; i0 += 1024) {
        int i = i0 + t; bool v = (i < PP);
        unsigned bits = v ? __float_as_uint(pmaxb[i]) : 0u;
        int key = (int)(bits >> 18);
        bool sel = v && ((key > BbA) || (key == BbA && (int)((bits >> 6) & 0xFFF) >= Bb2A));
        unsigned ball = __ballot_sync(0xffffffffu, sel);
        int base = 0;
        if (lane == 0 && ball) base = atomicAdd(&s_cnt, __popc(ball));
        base = __shfl_sync(0xffffffffu, base, 0);
        if (sel) {
            int p = base + __popc(ball & lt);
            if (p < SELCAP) g_selidx[b * SELCAP + p] = i;
        }
    }
    __syncthreads();
    if (t == 0) {
        g_selcnt[b] = min(s_cnt, SELCAP);
        g_tau[b * 2] = BbA;
        g_tau[b * 2 + 1] = Bb2A;
    }
}

// ---- kAB: softmax + candidate emit over preselected priors ----
__global__ void __launch_bounds__(256) kAB(const float* __restrict__ logits) {
    int b = blockIdx.y;
    int wib = blockIdx.x * 8 + (threadIdx.x >> 5);   // warp id in batch, 0..63
    int lane = threadIdx.x & 31;
    unsigned lt = (1u << lane) - 1u;
    int ns   = g_selcnt[b];
    int BbA  = g_tau[b * 2];
    int Bb2A = g_tau[b * 2 + 1];
    unsigned long long* kb = g_keys + (size_t)b * KEYCAP;

    for (int slot = wib; slot < ns; slot += 64) {
        int prior = g_selidx[b * SELCAP + slot];
        const float* row = logits + ((size_t)b * PP + prior) * CC;
        float x0 = __ldg(row + lane);
        float x1 = __ldg(row + 32 + lane);
        float x2 = (lane < 17) ? __ldg(row + 64 + lane) : -3.0e38f;
        float m = ord2f(__reduce_max_sync(0xffffffffu, f2ord(fmaxf(x0, fmaxf(x1, x2)))));
        float e0 = expf(x0 - m);
        float e1 = expf(x1 - m);
        float e2 = (lane < 17) ? expf(x2 - m) : 0.0f;
        float s = e0 + e1 + e2;
#pragma unroll
        for (int o = 16; o; o >>= 1) s += __shfl_xor_sync(0xffffffffu, s, o);
        float sc0 = e0 / s, sc1 = e1 / s, sc2 = e2 / s;
        unsigned b0 = __float_as_uint(sc0), b1 = __float_as_uint(sc1), b2 = __float_as_uint(sc2);
        int k0 = (int)(b0 >> 18), k1v = (int)(b1 >> 18), k2v = (int)(b2 >> 18);
        bool c0 = (lane > 0)  && ((k0 > BbA)  || (k0 == BbA  && (int)((b0 >> 6) & 0xFFF) >= Bb2A));
        bool c1 =                ((k1v > BbA) || (k1v == BbA && (int)((b1 >> 6) & 0xFFF) >= Bb2A));
        bool c2 = (lane < 17) && ((k2v > BbA) || (k2v == BbA && (int)((b2 >> 6) & 0xFFF) >= Bb2A));
        unsigned ba0 = __ballot_sync(0xffffffffu, c0);
        unsigned ba1 = __ballot_sync(0xffffffffu, c1);
        unsigned ba2 = __ballot_sync(0xffffffffu, c2);
        int n0 = __popc(ba0), n1 = __popc(ba1), n2 = __popc(ba2);
        int base = 0;
        if (lane == 0 && (n0 + n1 + n2)) base = atomicAdd(&g_cnt[b], n0 + n1 + n2);
        base = __shfl_sync(0xffffffffu, base, 0);
        unsigned fb = (unsigned)prior * FG;
        if (c0) {
            int p = base + __popc(ba0 & lt);
            if (p < KEYCAP) kb[p] = ((unsigned long long)(~b0) << 32) | (fb + lane - 1);
        }
        if (c1) {
            int p = base + n0 + __popc(ba1 & lt);
            if (p < KEYCAP) kb[p] = ((unsigned long long)(~b1) << 32) | (fb + 31 + lane);
        }
        if (c2) {
            int p = base + n0 + n1 + __popc(ba2 & lt);
            if (p < KEYCAP) kb[p] = ((unsigned long long)(~b2) << 32) | (fb + 63 + lane);
        }
    }
}

// bitonic sort n (pow2 >= 64, <= 4096) u64 keys ascending; block = 1024 thr
__device__ __forceinline__ void bitonic(unsigned long long* keys, int n) {
    int t = threadIdx.x;
    for (int base = t; base < n; base += 1024) {
        unsigned long long key = keys[base];
#pragma unroll
        for (int k2 = 2; k2 <= 32; k2 <<= 1) {
            bool up = ((base & k2) == 0);
#pragma unroll
            for (int j = k2 >> 1; j >= 1; j >>= 1) {
                unsigned long long other = __shfl_xor_sync(0xffffffffu, key, j);
                bool keepSmall = (((base & j) == 0) == up);
                bool take = keepSmall ? (other < key) : (other > key);
                if (take) key = other;
            }
        }
        keys[base] = key;
    }
    __syncthreads();
    for (int k = 64; k <= n; k <<= 1) {
        for (int j = k >> 1; j >= 32; j >>= 1) {
            for (int u = t; u < (n >> 1); u += 1024) {
                int i = ((u & ~(j - 1)) << 1) | (u & (j - 1));
                int p = i | j;
                unsigned long long a = keys[i], bk = keys[p];
                bool up = ((i & k) == 0);
                if ((a > bk) == up) { keys[i] = bk; keys[p] = a; }
            }
            __syncthreads();
        }
        for (int base = t; base < n; base += 1024) {
            unsigned long long key = keys[base];
            bool up = ((base & k) == 0);
#pragma unroll
            for (int j = 16; j >= 1; j >>= 1) {
                unsigned long long other = __shfl_xor_sync(0xffffffffu, key, j);
                bool keepSmall = (((base & j) == 0) == up);
                bool take = keepSmall ? (other < key) : (other > key);
                if (take) key = other;
            }
            keys[base] = key;
        }
        __syncthreads();
    }
}

// ---------------- kC smem layout ----------------
#define OFFC_KEYS  0         // 4096 u64 = 32768
#define OFFC_F     32768     // obox4 6400 + ar 1600 + 5*1600 = 16000
#define OFFC_CL    48768     // 1600
#define OFFC_MASK  50368     // 20800
#define DYN_C      71168

// ---- kC: per-batch sort -> decode -> IoU -> NMS -> top-100 output ----
__global__ void __launch_bounds__(1024) kC(const float* __restrict__ bbox,
                                           const float* __restrict__ priors,
                                           float* __restrict__ out) {
    extern __shared__ unsigned char dyn[];
    unsigned long long* keys = (unsigned long long*)(dyn + OFFC_KEYS);
    float4* obox4 = (float4*)(dyn + OFFC_F);
    float*  ar    = (float*)(dyn + OFFC_F + 6400);
    float*  bx1   = (float*)(dyn + OFFC_F + 8000);
    float*  by1   = bx1 + 400;
    float*  bx2   = by1 + 400;
    float*  by2   = bx2 + 400;
    float*  tv    = by2 + 400;
    int*       cl   = (int*)(dyn + OFFC_CL);
    unsigned*  mask = (unsigned*)(dyn + OFFC_MASK);

    __shared__ int s_n;
    __shared__ unsigned initm[NW], livem[NW], finm[NW];
    __shared__ int fi[MAXDET], warpcnt[32], warpoff[33];

    int b = blockIdx.x, t = threadIdx.x, lane = t & 31, w = t >> 5;
    unsigned lt = (1u << lane) - 1u;

    if (t == 0) { s_n = g_cnt[b]; g_cnt[b] = 0; }       // read + replay re-zero
    __syncthreads();
    int cnt = min(s_n, KEYCAP);
    for (int i = t; i < KEYCAP; i += 1024)
        keys[i] = (i < cnt) ? g_keys[(size_t)b * KEYCAP + i] : 0xFFFFFFFFFFFFFFFFull;
    __syncthreads();
    int sortn = 512;
    while (sortn < cnt) sortn <<= 1;
    bitonic(keys, sortn);

    // decode top-400
    if (t < PRE_K) {
        unsigned long long key = keys[t];
        unsigned bits = ~(unsigned)(key >> 32);
        float v = __uint_as_float(bits);
        int fidx = (int)(key & 0xFFFFFFFFull);
        if (fidx < 0 || fidx >= PP * FG) { fidx = 0; v = 0.0f; }
        int prior = fidx / FG;
        int c = fidx - prior * FG + 1;
        tv[t] = v; cl[t] = c;
        const float* L  = bbox   + ((size_t)b * PP + prior) * 4;
        const float* Pr = priors + (size_t)prior * 4;
        float px = Pr[0], py = Pr[1], pw = Pr[2], ph = Pr[3];
        float cx = L[0] * 0.1f * pw + px;
        float cy = L[1] * 0.1f * ph + py;
        float sw = expf(L[2] * 0.2f) * pw;
        float sh = expf(L[3] * 0.2f) * ph;
        float X1 = (cx - sw * 0.5f) * Wf, Y1 = (cy - sh * 0.5f) * Hf;
        float X2 = (cx + sw * 0.5f) * Wf, Y2 = (cy + sh * 0.5f) * Hf;
        bx1[t] = X1; by1[t] = Y1; bx2[t] = X2; by2[t] = Y2;
        float off = (float)c * OFFC;
        float a1 = X1 + off, a2 = Y1 + off, a3 = X2 + off, a4 = Y2 + off;
        obox4[t] = make_float4(a1, a2, a3, a4);
        ar[t] = (a3 - a1) * (a4 - a2);
    }
    __syncthreads();
    // IoU masks: float4 LDS, FMA sign test with predicated exact-div fallback
    {
        const int ITER = (NW * PRE_K + 1023) / 1024;   // 6
#pragma unroll
        for (int ii = 0; ii < ITER; ii++) {
            int idx = ii * 1024 + t;
            bool valid = (idx < NW * PRE_K);
            int vidx = valid ? idx : 0;
            int wrd = vidx / PRE_K;
            int i   = vidx - wrd * PRE_K;
            int j0  = wrd * 32;
            unsigned bst = (unsigned)max(0, min(32, i + 1 - j0));
            unsigned bmin = __reduce_min_sync(0xffffffffu, bst);
            float4 oi = obox4[i];
            float a = ar[i];
            unsigned mm = 0;
            for (unsigned bit = bmin; bit < 32; bit++) {
                int j = j0 + (int)bit;
                bool act = valid && (j > i) && (j < PRE_K);
                int js = (j < PRE_K) ? j : 0;
                float4 oj = obox4[js];
                float ltx = fmaxf(oi.x, oj.x);
                float lty = fmaxf(oi.y, oj.y);
                float rbx = fminf(oi.z, oj.z);
                float rby = fminf(oi.w, oj.w);
                float wv = fmaxf(rbx - ltx, 0.0f);
                float hv = fmaxf(rby - lty, 0.0f);
                float inter = wv * hv;
                float denom = a + ar[js] - inter + 1e-9f;
                float diff = fmaf(-NMST, denom, inter);
                bool sup = (diff > 0.0f);
                if (act && fabsf(diff) <= 3e-7f * denom)   // rare; predicated div
                    sup = (inter / denom) > NMST;
                if (act && sup) mm |= 1u << bit;
            }
            if (valid) mask[i * NW + wrd] = mm;
        }
    }
    __syncthreads();
    if (w < NW) {
        bool rm = true, nz = false;
        if (t < PRE_K) {
            rm = !(tv[t] > CONF);
            unsigned o = 0;
#pragma unroll
            for (int k = 0; k < NW; k++) o |= mask[t * NW + k];
            nz = (o != 0);
        }
        unsigned br = __ballot_sync(0xffffffffu, rm);
        unsigned bn = __ballot_sync(0xffffffffu, nz);
        if (lane == 0) { initm[w] = br; livem[w] = bn; }
    }
    __syncthreads();
    if (w == 0) {   // serial greedy walk, nz-skip (exact)
        unsigned remv = (lane < NW) ? initm[lane] : 0u;
        for (int w13 = 0; w13 < NW; w13++) {
            unsigned live = livem[w13];
            while (live) {
                int bit = __ffs(live) - 1;
                live &= live - 1;
                int i = w13 * 32 + bit;
                unsigned word = __shfl_sync(0xffffffffu, remv, w13);
                if (!((word >> bit) & 1u)) {
                    unsigned rowm = (lane < NW) ? mask[i * NW + lane] : 0u;
                    remv |= rowm;
                }
            }
        }
        if (lane < NW) finm[lane] = remv;
    }
    __syncthreads();
    bool kp = false;
    if (t < PRE_K) kp = !((finm[t >> 5] >> (t & 31)) & 1u);
    unsigned ball = __ballot_sync(0xffffffffu, kp);
    if (lane == 0) warpcnt[w] = __popc(ball);
    __syncthreads();
    if (t == 0) {
        int acc = 0;
        for (int i = 0; i < 32; i++) { warpoff[i] = acc; acc += warpcnt[i]; }
        warpoff[32] = acc;
    }
    __syncthreads();
    int nk = warpoff[32];
    if (t < PRE_K) {
        int rk = warpoff[w] + __popc(ball & lt);
        int pos = kp ? rk : nk + (t - rk);
        if (pos < MAXDET) fi[pos] = t;
    }
    __syncthreads();
    if (t < MAXDET) {
        int j = fi[t];
        bool kj = !((finm[j >> 5] >> (j & 31)) & 1u);
        int base = (b * MAXDET + t) * 4;
        out[base + 0] = bx1[j];
        out[base + 1] = by1[j];
        out[base + 2] = bx2[j];
        out[base + 3] = by2[j];
        out[BB * MAXDET * 4 + b * MAXDET + t] = (float)cl[j];
        out[BB * MAXDET * 5 + b * MAXDET + t] = kj ? tv[j] : 0.0f;
    }
}

// ------------------------------ launcher -----------------------------------
extern "C" void kernel_launch(void* const* d_in, const int* in_sizes, int n_in,
                              void* d_out, int out_size) {
    const float* logits = (const float*)d_in[0];
    const float* bbox   = (const float*)d_in[1];
    const float* priors = (const float*)d_in[2];
    float* out = (float*)d_out;

    cudaFuncSetAttribute(kC, cudaFuncAttributeMaxDynamicSharedMemorySize, DYN_C);

    int totalWarps = (BB * PP) / G;            // 40832 warps, 8 rows each
    int blocks = (totalWarps * 32 + 255) / 256;
    k1_priormax<<<blocks, 256>>>(logits);
    kTau<<<BB, 1024>>>();
    kAB<<<dim3(8, BB), 256>>>(logits);
    kC<<<BB, 1024, DYN_C>>>(bbox, priors, out);
}

// round 15
// speedup vs baseline: 1.1945x; 1.1945x over previous
#include <cuda_runtime.h>
#include <cstdint>
#include <math.h>

#define BB      32
#define PP      10208
#define CC      81
#define FG      80
#define PRE_K   400
#define MAXDET  100
#define KEYCAP  4096
#define NBINS   4096
#define SLICE   1276        // 8 slices * 1276 = 10208
#define SELC    1280
#define CONF    0.01f
#define NMST    0.45f
#define Wf      1280.0f
#define Hf      1024.0f
#define OFFC    1281.0f
#define G       8
#define NW      13

// ---------------- global scratch (zero-initialized device globals) ---------
__device__ float              g_pmax[BB * PP];
__device__ unsigned           g_hist[BB * NBINS];  // kC re-zeros after use
__device__ unsigned long long g_keys[BB * KEYCAP];
__device__ int                g_cnt[BB];           // kC re-zeros after use

// order-preserving float<->uint maps
__device__ __forceinline__ unsigned f2ord(float f) {
    unsigned u = __float_as_uint(f);
    return (u & 0x80000000u) ? ~u : (u | 0x80000000u);
}
__device__ __forceinline__ float ord2f(unsigned v) {
    unsigned u = (v & 0x80000000u) ? (v ^ 0x80000000u) : ~v;
    return __uint_as_float(u);
}

// -- K1: per-prior max fg score = 1/sum(exp(xi-mf)); 8 rows/warp, MLP=24;
//    launch_bounds(256,4) -> 64 regs so the 24-load batch stays in registers.
//    Also builds per-batch coarse histogram via global RED.ADD --
__global__ void __launch_bounds__(256, 4) k1_priormax(const float* __restrict__ logits) {
    int wid  = (blockIdx.x * blockDim.x + threadIdx.x) >> 5;
    int lane = threadIdx.x & 31;
    int row  = wid * G;
    if (row >= BB * PP) return;
    const float* p = logits + (size_t)row * CC;
    float a0[G], a1[G], a2[G];
#pragma unroll
    for (int g = 0; g < G; g++) {
        a0[g] = __ldg(p + g * CC + lane);
        a1[g] = __ldg(p + g * CC + 32 + lane);
        a2[g] = (lane < 17) ? __ldg(p + g * CC + 64 + lane) : -3.0e38f;
    }
    float keep = 0.0f;
#pragma unroll
    for (int g = 0; g < G; g++) {
        float xf = fmaxf((lane == 0) ? -3.0e38f : a0[g], fmaxf(a1[g], a2[g]));
        float mf = ord2f(__reduce_max_sync(0xffffffffu, f2ord(xf)));
        float s = __expf(a0[g] - mf) + __expf(a1[g] - mf) +
                  ((lane < 17) ? __expf(a2[g] - mf) : 0.0f);
#pragma unroll
        for (int o = 16; o; o >>= 1) s += __shfl_xor_sync(0xffffffffu, s, o);
        float r = __fdividef(1.0f, s);
        if (lane == g) keep = r;
    }
    if (lane < G) {
        g_pmax[row + lane] = keep;
        int b = row / PP;
        atomicAdd(&g_hist[b * NBINS + (__float_as_uint(keep) >> 18)], 1u);
    }
}

// boundary: largest bin Bb with count(bins >= Bb) >= T; *s_above = strictly above
// (requires 1024-thread block)
__device__ __forceinline__ int boundary(const unsigned* __restrict__ h, int T,
                                        int* s_minR, unsigned* s_above,
                                        unsigned* s_wsum) {
    int t = threadIdx.x, lane = t & 31, w = t >> 5;
    __syncthreads();
    if (t == 0) { *s_minR = 0x7fffffff; *s_above = 0u; }
    __syncthreads();
    int base = 4095 - 4 * t;
    unsigned c0 = h[base], c1 = h[base - 1], c2 = h[base - 2], c3 = h[base - 3];
    unsigned part = c0 + c1 + c2 + c3;
    unsigned v = part;
#pragma unroll
    for (int o = 1; o < 32; o <<= 1) {
        unsigned u = __shfl_up_sync(0xffffffffu, v, o);
        if (lane >= o) v += u;
    }
    if (lane == 31) s_wsum[w] = v;
    __syncthreads();
    if (w == 0) {
        unsigned x = s_wsum[lane];
#pragma unroll
        for (int o = 1; o < 32; o <<= 1) {
            unsigned u = __shfl_up_sync(0xffffffffu, x, o);
            if (lane >= o) x += u;
        }
        s_wsum[lane] = x;
    }
    __syncthreads();
    unsigned excl = ((w > 0) ? s_wsum[w - 1] : 0u) + (v - part);
    unsigned cum = excl, myAbove = 0;
    int myR = 0x7fffffff;
    unsigned cs[4] = {c0, c1, c2, c3};
#pragma unroll
    for (int i2 = 0; i2 < 4; i2++) {
        unsigned prev = cum;
        cum += cs[i2];
        if (myR == 0x7fffffff && cum >= (unsigned)T) { myR = 4 * t + i2; myAbove = prev; }
    }
    if (myR != 0x7fffffff) atomicMin(s_minR, myR);
    __syncthreads();
    int r = *s_minR;
    if (r == myR && myR != 0x7fffffff) *s_above = myAbove;
    __syncthreads();
    return (r == 0x7fffffff) ? 0 : (4095 - r);
}

// bitonic sort n (pow2 >= 64, <= 4096) u64 keys ascending; block = 1024 thr
__device__ __forceinline__ void bitonic(unsigned long long* keys, int n) {
    int t = threadIdx.x;
    for (int base = t; base < n; base += 1024) {
        unsigned long long key = keys[base];
#pragma unroll
        for (int k2 = 2; k2 <= 32; k2 <<= 1) {
            bool up = ((base & k2) == 0);
#pragma unroll
            for (int j = k2 >> 1; j >= 1; j >>= 1) {
                unsigned long long other = __shfl_xor_sync(0xffffffffu, key, j);
                bool keepSmall = (((base & j) == 0) == up);
                bool take = keepSmall ? (other < key) : (other > key);
                if (take) key = other;
            }
        }
        keys[base] = key;
    }
    __syncthreads();
    for (int k = 64; k <= n; k <<= 1) {
        for (int j = k >> 1; j >= 32; j >>= 1) {
            for (int u = t; u < (n >> 1); u += 1024) {
                int i = ((u & ~(j - 1)) << 1) | (u & (j - 1));
                int p = i | j;
                unsigned long long a = keys[i], bk = keys[p];
                bool up = ((i & k) == 0);
                if ((a > bk) == up) { keys[i] = bk; keys[p] = a; }
            }
            __syncthreads();
        }
        for (int base = t; base < n; base += 1024) {
            unsigned long long key = keys[base];
            bool up = ((base & k) == 0);
#pragma unroll
            for (int j = 16; j >= 1; j >>= 1) {
                unsigned long long other = __shfl_xor_sync(0xffffffffu, key, j);
                bool keepSmall = (((base & j) == 0) == up);
                bool take = keepSmall ? (other < key) : (other > key);
                if (take) key = other;
            }
            keys[base] = key;
        }
        __syncthreads();
    }
}

// ---- kAB: 8 blocks per batch; tau -> select slice -> softmax -> emit keys ----
__global__ void __launch_bounds__(1024) kAB(const float* __restrict__ logits) {
    __shared__ unsigned hist[NBINS];
    __shared__ int selidx[SELC];
    __shared__ unsigned s_wsum[32];
    __shared__ int s_minR, s_cnt;
    __shared__ unsigned s_above;

    int b = blockIdx.y, t = threadIdx.x, lane = t & 31, w = t >> 5;
    unsigned lt = (1u << lane) - 1u;
    int s0 = blockIdx.x * SLICE;
    int s1 = min(s0 + SLICE, PP);
    const float* pmaxb = g_pmax + b * PP;

    if (t == 0) s_cnt = 0;
    for (int i = t; i < NBINS; i += 1024) hist[i] = g_hist[b * NBINS + i];
    // boundary() starts with __syncthreads -> hist loads visible
    int BbA = boundary(hist, PRE_K, &s_minR, &s_above, s_wsum);
    int needA = PRE_K - (int)s_above;
    for (int i = t; i < NBINS; i += 1024) hist[i] = 0u;
    __syncthreads();
    for (int i = t; i < PP; i += 1024) {             // full-PP fine pass
        unsigned bits = __float_as_uint(pmaxb[i]);
        if ((int)(bits >> 18) == BbA) atomicAdd(&hist[(bits >> 6) & 0xFFF], 1u);
    }
    int Bb2A = boundary(hist, needA, &s_minR, &s_above, s_wsum);
    if (Bb2A > 0) Bb2A--;            // one fine-bin slack (covers k1 __expf noise)

    // select priors in this slice with pmax >= tau
    for (int ii = 0; ii < 2; ii++) {
        int i = s0 + ii * 1024 + t;
        bool v = (i < s1);
        unsigned bits = v ? __float_as_uint(pmaxb[i]) : 0u;
        int key = (int)(bits >> 18);
        bool sel = v && ((key > BbA) || (key == BbA && (int)((bits >> 6) & 0xFFF) >= Bb2A));
        unsigned ball = __ballot_sync(0xffffffffu, sel);
        int base = 0;
        if (lane == 0 && ball) base = atomicAdd(&s_cnt, __popc(ball));
        base = __shfl_sync(0xffffffffu, base, 0);
        if (sel) {
            int p = base + __popc(ball & lt);
            if (p < SELC) selidx[p] = i;
        }
    }
    __syncthreads();
    int ns = min(s_cnt, SELC);

    // exact softmax on selected priors; emit candidate keys to global
    for (int slot = w; slot < ns; slot += 32) {
        int prior = selidx[slot];
        const float* row = logits + ((size_t)b * PP + prior) * CC;
        float x0 = __ldg(row + lane);
        float x1 = __ldg(row + 32 + lane);
        float x2 = (lane < 17) ? __ldg(row + 64 + lane) : -3.0e38f;
        float m = ord2f(__reduce_max_sync(0xffffffffu, f2ord(fmaxf(x0, fmaxf(x1, x2)))));
        float e0 = expf(x0 - m);
        float e1 = expf(x1 - m);
        float e2 = (lane < 17) ? expf(x2 - m) : 0.0f;
        float s = e0 + e1 + e2;
#pragma unroll
        for (int o = 16; o; o >>= 1) s += __shfl_xor_sync(0xffffffffu, s, o);
        float sc0 = e0 / s, sc1 = e1 / s, sc2 = e2 / s;
        unsigned b0 = __float_as_uint(sc0), b1 = __float_as_uint(sc1), b2 = __float_as_uint(sc2);
        int k0 = (int)(b0 >> 18), k1v = (int)(b1 >> 18), k2v = (int)(b2 >> 18);
        bool c0 = (lane > 0)  && ((k0 > BbA)  || (k0 == BbA  && (int)((b0 >> 6) & 0xFFF) >= Bb2A));
        bool c1 =                ((k1v > BbA) || (k1v == BbA && (int)((b1 >> 6) & 0xFFF) >= Bb2A));
        bool c2 = (lane < 17) && ((k2v > BbA) || (k2v == BbA && (int)((b2 >> 6) & 0xFFF) >= Bb2A));
        unsigned ba0 = __ballot_sync(0xffffffffu, c0);
        unsigned ba1 = __ballot_sync(0xffffffffu, c1);
        unsigned ba2 = __ballot_sync(0xffffffffu, c2);
        int n0 = __popc(ba0), n1 = __popc(ba1), n2 = __popc(ba2);
        int base = 0;
        if (lane == 0 && (n0 + n1 + n2)) base = atomicAdd(&g_cnt[b], n0 + n1 + n2);
        base = __shfl_sync(0xffffffffu, base, 0);
        unsigned fb = (unsigned)prior * FG;
        unsigned long long* kb = g_keys + (size_t)b * KEYCAP;
        if (c0) {
            int p = base + __popc(ba0 & lt);
            if (p < KEYCAP) kb[p] = ((unsigned long long)(~b0) << 32) | (fb + lane - 1);
        }
        if (c1) {
            int p = base + n0 + __popc(ba1 & lt);
            if (p < KEYCAP) kb[p] = ((unsigned long long)(~b1) << 32) | (fb + 31 + lane);
        }
        if (c2) {
            int p = base + n0 + n1 + __popc(ba2 & lt);
            if (p < KEYCAP) kb[p] = ((unsigned long long)(~b2) << 32) | (fb + 63 + lane);
        }
    }
}

// ---------------- kC smem layout ----------------
#define OFFC_KEYS  0         // 4096 u64 = 32768
#define OFFC_F     32768     // obox4 6400 + ar 1600 + 5*1600 = 16000
#define OFFC_CL    48768     // 1600
#define OFFC_MASK  50368     // 20800
#define DYN_C      71168

// ---- kC: per-batch sort -> decode -> IoU -> NMS -> top-100 output ----
__global__ void __launch_bounds__(1024) kC(const float* __restrict__ bbox,
                                           const float* __restrict__ priors,
                                           float* __restrict__ out) {
    extern __shared__ unsigned char dyn[];
    unsigned long long* keys = (unsigned long long*)(dyn + OFFC_KEYS);
    float4* obox4 = (float4*)(dyn + OFFC_F);
    float*  ar    = (float*)(dyn + OFFC_F + 6400);
    float*  bx1   = (float*)(dyn + OFFC_F + 8000);
    float*  by1   = bx1 + 400;
    float*  bx2   = by1 + 400;
    float*  by2   = bx2 + 400;
    float*  tv    = by2 + 400;
    int*       cl   = (int*)(dyn + OFFC_CL);
    unsigned*  mask = (unsigned*)(dyn + OFFC_MASK);

    __shared__ int s_n;
    __shared__ unsigned initm[NW], livem[NW], finm[NW];
    __shared__ int fi[MAXDET], warpcnt[32], warpoff[33];

    int b = blockIdx.x, t = threadIdx.x, lane = t & 31, w = t >> 5;
    unsigned lt = (1u << lane) - 1u;

    if (t == 0) { s_n = g_cnt[b]; g_cnt[b] = 0; }       // read + replay re-zero
    for (int i = t; i < NBINS; i += 1024) g_hist[b * NBINS + i] = 0u;
    __syncthreads();
    int cnt = min(s_n, KEYCAP);
    int sortn = 512;
    while (sortn < cnt) sortn <<= 1;
    // init/load only the sortn keys we'll sort
    for (int i = t; i < sortn; i += 1024)
        keys[i] = (i < cnt) ? g_keys[(size_t)b * KEYCAP + i] : 0xFFFFFFFFFFFFFFFFull;
    __syncthreads();
    bitonic(keys, sortn);

    // decode top-400
    if (t < PRE_K) {
        unsigned long long key = keys[t];
        unsigned bits = ~(unsigned)(key >> 32);
        float v = __uint_as_float(bits);
        int fidx = (int)(key & 0xFFFFFFFFull);
        if (fidx < 0 || fidx >= PP * FG) { fidx = 0; v = 0.0f; }
        int prior = fidx / FG;
        int c = fidx - prior * FG + 1;
        tv[t] = v; cl[t] = c;
        const float* L  = bbox   + ((size_t)b * PP + prior) * 4;
        const float* Pr = priors + (size_t)prior * 4;
        float px = Pr[0], py = Pr[1], pw = Pr[2], ph = Pr[3];
        float cx = L[0] * 0.1f * pw + px;
        float cy = L[1] * 0.1f * ph + py;
        float sw = expf(L[2] * 0.2f) * pw;
        float sh = expf(L[3] * 0.2f) * ph;
        float X1 = (cx - sw * 0.5f) * Wf, Y1 = (cy - sh * 0.5f) * Hf;
        float X2 = (cx + sw * 0.5f) * Wf, Y2 = (cy + sh * 0.5f) * Hf;
        bx1[t] = X1; by1[t] = Y1; bx2[t] = X2; by2[t] = Y2;
        float off = (float)c * OFFC;
        float a1 = X1 + off, a2 = Y1 + off, a3 = X2 + off, a4 = Y2 + off;
        obox4[t] = make_float4(a1, a2, a3, a4);
        ar[t] = (a3 - a1) * (a4 - a2);
    }
    __syncthreads();
    // IoU masks: float4 LDS, FMA sign test with predicated exact-div fallback
    {
        const int ITER = (NW * PRE_K + 1023) / 1024;   // 6
#pragma unroll
        for (int ii = 0; ii < ITER; ii++) {
            int idx = ii * 1024 + t;
            bool valid = (idx < NW * PRE_K);
            int vidx = valid ? idx : 0;
            int wrd = vidx / PRE_K;
            int i   = vidx - wrd * PRE_K;
            int j0  = wrd * 32;
            unsigned bst = (unsigned)max(0, min(32, i + 1 - j0));
            unsigned bmin = __reduce_min_sync(0xffffffffu, bst);
            float4 oi = obox4[i];
            float a = ar[i];
            unsigned mm = 0;
            for (unsigned bit = bmin; bit < 32; bit++) {
                int j = j0 + (int)bit;
                bool act = valid && (j > i) && (j < PRE_K);
                int js = (j < PRE_K) ? j : 0;
                float4 oj = obox4[js];
                float ltx = fmaxf(oi.x, oj.x);
                float lty = fmaxf(oi.y, oj.y);
                float rbx = fminf(oi.z, oj.z);
                float rby = fminf(oi.w, oj.w);
                float wv = fmaxf(rbx - ltx, 0.0f);
                float hv = fmaxf(rby - lty, 0.0f);
                float inter = wv * hv;
                float denom = a + ar[js] - inter + 1e-9f;
                float diff = fmaf(-NMST, denom, inter);
                bool sup = (diff > 0.0f);
                if (act && fabsf(diff) <= 3e-7f * denom)   // rare; predicated div
                    sup = (inter / denom) > NMST;
                if (act && sup) mm |= 1u << bit;
            }
            if (valid) mask[i * NW + wrd] = mm;
        }
    }
    __syncthreads();
    if (w < NW) {
        bool rm = true, nz = false;
        if (t < PRE_K) {
            rm = !(tv[t] > CONF);
            unsigned o = 0;
#pragma unroll
            for (int k = 0; k < NW; k++) o |= mask[t * NW + k];
            nz = (o != 0);
        }
        unsigned br = __ballot_sync(0xffffffffu, rm);
        unsigned bn = __ballot_sync(0xffffffffu, nz);
        if (lane == 0) { initm[w] = br; livem[w] = bn; }
    }
    __syncthreads();
    if (w == 0) {   // serial greedy walk, nz-skip (exact)
        unsigned remv = (lane < NW) ? initm[lane] : 0u;
        for (int w13 = 0; w13 < NW; w13++) {
            unsigned live = livem[w13];
            while (live) {
                int bit = __ffs(live) - 1;
                live &= live - 1;
                int i = w13 * 32 + bit;
                unsigned word = __shfl_sync(0xffffffffu, remv, w13);
                if (!((word >> bit) & 1u)) {
                    unsigned rowm = (lane < NW) ? mask[i * NW + lane] : 0u;
                    remv |= rowm;
                }
            }
        }
        if (lane < NW) finm[lane] = remv;
    }
    __syncthreads();
    bool kp = false;
    if (t < PRE_K) kp = !((finm[t >> 5] >> (t & 31)) & 1u);
    unsigned ball = __ballot_sync(0xffffffffu, kp);
    if (lane == 0) warpcnt[w] = __popc(ball);
    __syncthreads();
    if (t == 0) {
        int acc = 0;
        for (int i = 0; i < 32; i++) { warpoff[i] = acc; acc += warpcnt[i]; }
        warpoff[32] = acc;
    }
    __syncthreads();
    int nk = warpoff[32];
    if (t < PRE_K) {
        int rk = warpoff[w] + __popc(ball & lt);
        int pos = kp ? rk : nk + (t - rk);
        if (pos < MAXDET) fi[pos] = t;
    }
    __syncthreads();
    if (t < MAXDET) {
        int j = fi[t];
        bool kj = !((finm[j >> 5] >> (j & 31)) & 1u);
        int base = (b * MAXDET + t) * 4;
        out[base + 0] = bx1[j];
        out[base + 1] = by1[j];
        out[base + 2] = bx2[j];
        out[base + 3] = by2[j];
        out[BB * MAXDET * 4 + b * MAXDET + t] = (float)cl[j];
        out[BB * MAXDET * 5 + b * MAXDET + t] = kj ? tv[j] : 0.0f;
    }
}

// ------------------------------ launcher -----------------------------------
extern "C" void kernel_launch(void* const* d_in, const int* in_sizes, int n_in,
                              void* d_out, int out_size) {
    const float* logits = (const float*)d_in[0];
    const float* bbox   = (const float*)d_in[1];
    const float* priors = (const float*)d_in[2];
    float* out = (float*)d_out;

    cudaFuncSetAttribute(kC, cudaFuncAttributeMaxDynamicSharedMemorySize, DYN_C);

    int totalWarps = (BB * PP) / G;            // 40832 warps, 8 rows each
    int blocks = (totalWarps * 32 + 255) / 256;
    k1_priormax<<<blocks, 256>>>(logits);
    kAB<<<dim3(8, BB), 1024>>>(logits);
    kC<<<BB, 1024, DYN_C>>>(bbox, priors, out);
}

// round 16
// speedup vs baseline: 1.2094x; 1.0125x over previous
#include <cuda_runtime.h>
#include <cstdint>
#include <math.h>

#define BB      32
#define PP      10208
#define CC      81
#define FG      80
#define PRE_K   400
#define MAXDET  100
#define KEYCAP  4096
#define NBINS   4096
#define SLICE   1276        // 8 slices * 1276 = 10208
#define SELC    1280
#define CONF    0.01f
#define NMST    0.45f
#define Wf      1280.0f
#define Hf      1024.0f
#define OFFC    1281.0f
#define G       8
#define NW      13

// ---------------- global scratch (zero-initialized device globals) ---------
__device__ float              g_pmax[BB * PP];
__device__ unsigned           g_hist[BB * NBINS];  // kC re-zeros after use
__device__ unsigned long long g_keys[BB * KEYCAP];
__device__ int                g_cnt[BB];           // kC re-zeros after use

// order-preserving float<->uint maps
__device__ __forceinline__ unsigned f2ord(float f) {
    unsigned u = __float_as_uint(f);
    return (u & 0x80000000u) ? ~u : (u | 0x80000000u);
}
__device__ __forceinline__ float ord2f(unsigned v) {
    unsigned u = (v & 0x80000000u) ? (v ^ 0x80000000u) : ~v;
    return __uint_as_float(u);
}

// -- K1: per-prior max fg score = exp(mf)/sum(exp(xi)); HALF-WARP layout:
//    lanes 0-15 own row r, lanes 16-31 own r+1 -> one 4-level reduction
//    serves TWO rows. 8 rows/warp as 4 pairs, all 24 loads batched.
//    Also builds per-batch coarse histogram via global RED.ADD --
__global__ void __launch_bounds__(256) k1_priormax(const float* __restrict__ logits) {
    int wid  = (blockIdx.x * blockDim.x + threadIdx.x) >> 5;
    int lane = threadIdx.x & 31;
    int row0 = wid * G;
    if (row0 >= BB * PP) return;
    int hl = lane & 15, half = lane >> 4;
    const float* base = logits + (size_t)(row0 + half) * CC + hl;
    float v[4][6];
#pragma unroll
    for (int p = 0; p < 4; p++) {               // 24 loads in flight
        const float* ptr = base + (size_t)(2 * p) * CC;
        v[p][0] = __ldg(ptr);
        v[p][1] = __ldg(ptr + 16);
        v[p][2] = __ldg(ptr + 32);
        v[p][3] = __ldg(ptr + 48);
        v[p][4] = __ldg(ptr + 64);
        v[p][5] = (hl == 0) ? __ldg(ptr + 80) : 0.0f;   // element 80 (class 80)
    }
    float keep = 0.0f;
#pragma unroll
    for (int p = 0; p < 4; p++) {
        // sum of exp over ALL 81 classes (no max subtraction; |logit| small)
        float e5 = (hl == 0) ? __expf(v[p][5]) : 0.0f;
        float s = __expf(v[p][0]) + __expf(v[p][1]) + __expf(v[p][2])
                + __expf(v[p][3]) + __expf(v[p][4]) + e5;
        // max over foreground classes 1..80: k=1..4 always fg;
        // k=0 index hl -> fg iff hl>0; k=5 index 80 -> fg (hl==0 lane only)
        float mx = fmaxf(fmaxf(v[p][1], v[p][2]), fmaxf(v[p][3], v[p][4]));
        mx = (hl > 0) ? fmaxf(mx, v[p][0]) : fmaxf(mx, v[p][5]);
#pragma unroll
        for (int o = 1; o < 16; o <<= 1) {      // 4 levels, serves both rows
            s  += __shfl_xor_sync(0xffffffffu, s, o);
            mx = fmaxf(mx, __shfl_xor_sync(0xffffffffu, mx, o));
        }
        float pm = __fdividef(__expf(mx), s);
        float partner = __shfl_xor_sync(0xffffffffu, pm, 16);
        if (lane == 2 * p)     keep = pm;       // lower half holds row 2p
        if (lane == 2 * p + 1) keep = partner;  // partner = row 2p+1
    }
    if (lane < G) {
        g_pmax[row0 + lane] = keep;             // coalesced store
        int b = row0 / PP;                      // warp's 8 rows share one batch
        atomicAdd(&g_hist[b * NBINS + (__float_as_uint(keep) >> 18)], 1u);
    }
}

// boundary: largest bin Bb with count(bins >= Bb) >= T; *s_above = strictly above
// (requires 1024-thread block)
__device__ __forceinline__ int boundary(const unsigned* __restrict__ h, int T,
                                        int* s_minR, unsigned* s_above,
                                        unsigned* s_wsum) {
    int t = threadIdx.x, lane = t & 31, w = t >> 5;
    __syncthreads();
    if (t == 0) { *s_minR = 0x7fffffff; *s_above = 0u; }
    __syncthreads();
    int base = 4095 - 4 * t;
    unsigned c0 = h[base], c1 = h[base - 1], c2 = h[base - 2], c3 = h[base - 3];
    unsigned part = c0 + c1 + c2 + c3;
    unsigned v = part;
#pragma unroll
    for (int o = 1; o < 32; o <<= 1) {
        unsigned u = __shfl_up_sync(0xffffffffu, v, o);
        if (lane >= o) v += u;
    }
    if (lane == 31) s_wsum[w] = v;
    __syncthreads();
    if (w == 0) {
        unsigned x = s_wsum[lane];
#pragma unroll
        for (int o = 1; o < 32; o <<= 1) {
            unsigned u = __shfl_up_sync(0xffffffffu, x, o);
            if (lane >= o) x += u;
        }
        s_wsum[lane] = x;
    }
    __syncthreads();
    unsigned excl = ((w > 0) ? s_wsum[w - 1] : 0u) + (v - part);
    unsigned cum = excl, myAbove = 0;
    int myR = 0x7fffffff;
    unsigned cs[4] = {c0, c1, c2, c3};
#pragma unroll
    for (int i2 = 0; i2 < 4; i2++) {
        unsigned prev = cum;
        cum += cs[i2];
        if (myR == 0x7fffffff && cum >= (unsigned)T) { myR = 4 * t + i2; myAbove = prev; }
    }
    if (myR != 0x7fffffff) atomicMin(s_minR, myR);
    __syncthreads();
    int r = *s_minR;
    if (r == myR && myR != 0x7fffffff) *s_above = myAbove;
    __syncthreads();
    return (r == 0x7fffffff) ? 0 : (4095 - r);
}

// bitonic sort n (pow2 >= 64, <= 4096) u64 keys ascending; block = 1024 thr
__device__ __forceinline__ void bitonic(unsigned long long* keys, int n) {
    int t = threadIdx.x;
    for (int base = t; base < n; base += 1024) {
        unsigned long long key = keys[base];
#pragma unroll
        for (int k2 = 2; k2 <= 32; k2 <<= 1) {
            bool up = ((base & k2) == 0);
#pragma unroll
            for (int j = k2 >> 1; j >= 1; j >>= 1) {
                unsigned long long other = __shfl_xor_sync(0xffffffffu, key, j);
                bool keepSmall = (((base & j) == 0) == up);
                bool take = keepSmall ? (other < key) : (other > key);
                if (take) key = other;
            }
        }
        keys[base] = key;
    }
    __syncthreads();
    for (int k = 64; k <= n; k <<= 1) {
        for (int j = k >> 1; j >= 32; j >>= 1) {
            for (int u = t; u < (n >> 1); u += 1024) {
                int i = ((u & ~(j - 1)) << 1) | (u & (j - 1));
                int p = i | j;
                unsigned long long a = keys[i], bk = keys[p];
                bool up = ((i & k) == 0);
                if ((a > bk) == up) { keys[i] = bk; keys[p] = a; }
            }
            __syncthreads();
        }
        for (int base = t; base < n; base += 1024) {
            unsigned long long key = keys[base];
            bool up = ((base & k) == 0);
#pragma unroll
            for (int j = 16; j >= 1; j >>= 1) {
                unsigned long long other = __shfl_xor_sync(0xffffffffu, key, j);
                bool keepSmall = (((base & j) == 0) == up);
                bool take = keepSmall ? (other < key) : (other > key);
                if (take) key = other;
            }
            keys[base] = key;
        }
        __syncthreads();
    }
}

// ---- kAB: 8 blocks per batch; tau -> select slice -> softmax -> emit keys ----
__global__ void __launch_bounds__(1024) kAB(const float* __restrict__ logits) {
    __shared__ unsigned hist[NBINS];
    __shared__ int selidx[SELC];
    __shared__ unsigned s_wsum[32];
    __shared__ int s_minR, s_cnt;
    __shared__ unsigned s_above;

    int b = blockIdx.y, t = threadIdx.x, lane = t & 31, w = t >> 5;
    unsigned lt = (1u << lane) - 1u;
    int s0 = blockIdx.x * SLICE;
    int s1 = min(s0 + SLICE, PP);
    const float* pmaxb = g_pmax + b * PP;

    if (t == 0) s_cnt = 0;
    for (int i = t; i < NBINS; i += 1024) hist[i] = g_hist[b * NBINS + i];
    // boundary() starts with __syncthreads -> hist loads visible
    int BbA = boundary(hist, PRE_K, &s_minR, &s_above, s_wsum);
    int needA = PRE_K - (int)s_above;
    for (int i = t; i < NBINS; i += 1024) hist[i] = 0u;
    __syncthreads();
    for (int i = t; i < PP; i += 1024) {             // full-PP fine pass
        unsigned bits = __float_as_uint(pmaxb[i]);
        if ((int)(bits >> 18) == BbA) atomicAdd(&hist[(bits >> 6) & 0xFFF], 1u);
    }
    int Bb2A = boundary(hist, needA, &s_minR, &s_above, s_wsum);
    if (Bb2A > 0) Bb2A--;            // one fine-bin slack (covers k1 rounding noise)

    // select priors in this slice with pmax >= tau
    for (int ii = 0; ii < 2; ii++) {
        int i = s0 + ii * 1024 + t;
        bool v = (i < s1);
        unsigned bits = v ? __float_as_uint(pmaxb[i]) : 0u;
        int key = (int)(bits >> 18);
        bool sel = v && ((key > BbA) || (key == BbA && (int)((bits >> 6) & 0xFFF) >= Bb2A));
        unsigned ball = __ballot_sync(0xffffffffu, sel);
        int base = 0;
        if (lane == 0 && ball) base = atomicAdd(&s_cnt, __popc(ball));
        base = __shfl_sync(0xffffffffu, base, 0);
        if (sel) {
            int p = base + __popc(ball & lt);
            if (p < SELC) selidx[p] = i;
        }
    }
    __syncthreads();
    int ns = min(s_cnt, SELC);

    // exact softmax on selected priors; emit candidate keys to global
    for (int slot = w; slot < ns; slot += 32) {
        int prior = selidx[slot];
        const float* row = logits + ((size_t)b * PP + prior) * CC;
        float x0 = __ldg(row + lane);
        float x1 = __ldg(row + 32 + lane);
        float x2 = (lane < 17) ? __ldg(row + 64 + lane) : -3.0e38f;
        float m = ord2f(__reduce_max_sync(0xffffffffu, f2ord(fmaxf(x0, fmaxf(x1, x2)))));
        float e0 = expf(x0 - m);
        float e1 = expf(x1 - m);
        float e2 = (lane < 17) ? expf(x2 - m) : 0.0f;
        float s = e0 + e1 + e2;
#pragma unroll
        for (int o = 16; o; o >>= 1) s += __shfl_xor_sync(0xffffffffu, s, o);
        float sc0 = e0 / s, sc1 = e1 / s, sc2 = e2 / s;
        unsigned b0 = __float_as_uint(sc0), b1 = __float_as_uint(sc1), b2 = __float_as_uint(sc2);
        int k0 = (int)(b0 >> 18), k1v = (int)(b1 >> 18), k2v = (int)(b2 >> 18);
        bool c0 = (lane > 0)  && ((k0 > BbA)  || (k0 == BbA  && (int)((b0 >> 6) & 0xFFF) >= Bb2A));
        bool c1 =                ((k1v > BbA) || (k1v == BbA && (int)((b1 >> 6) & 0xFFF) >= Bb2A));
        bool c2 = (lane < 17) && ((k2v > BbA) || (k2v == BbA && (int)((b2 >> 6) & 0xFFF) >= Bb2A));
        unsigned ba0 = __ballot_sync(0xffffffffu, c0);
        unsigned ba1 = __ballot_sync(0xffffffffu, c1);
        unsigned ba2 = __ballot_sync(0xffffffffu, c2);
        int n0 = __popc(ba0), n1 = __popc(ba1), n2 = __popc(ba2);
        int base = 0;
        if (lane == 0 && (n0 + n1 + n2)) base = atomicAdd(&g_cnt[b], n0 + n1 + n2);
        base = __shfl_sync(0xffffffffu, base, 0);
        unsigned fb = (unsigned)prior * FG;
        unsigned long long* kb = g_keys + (size_t)b * KEYCAP;
        if (c0) {
            int p = base + __popc(ba0 & lt);
            if (p < KEYCAP) kb[p] = ((unsigned long long)(~b0) << 32) | (fb + lane - 1);
        }
        if (c1) {
            int p = base + n0 + __popc(ba1 & lt);
            if (p < KEYCAP) kb[p] = ((unsigned long long)(~b1) << 32) | (fb + 31 + lane);
        }
        if (c2) {
            int p = base + n0 + n1 + __popc(ba2 & lt);
            if (p < KEYCAP) kb[p] = ((unsigned long long)(~b2) << 32) | (fb + 63 + lane);
        }
    }
}

// ---------------- kC smem layout ----------------
#define OFFC_KEYS  0         // 4096 u64 = 32768
#define OFFC_F     32768     // obox4 6400 + ar 1600 + 5*1600 = 16000
#define OFFC_CL    48768     // 1600
#define OFFC_MASK  50368     // 20800
#define DYN_C      71168

// ---- kC: per-batch sort -> decode -> IoU -> NMS -> top-100 output ----
__global__ void __launch_bounds__(1024) kC(const float* __restrict__ bbox,
                                           const float* __restrict__ priors,
                                           float* __restrict__ out) {
    extern __shared__ unsigned char dyn[];
    unsigned long long* keys = (unsigned long long*)(dyn + OFFC_KEYS);
    float4* obox4 = (float4*)(dyn + OFFC_F);
    float*  ar    = (float*)(dyn + OFFC_F + 6400);
    float*  bx1   = (float*)(dyn + OFFC_F + 8000);
    float*  by1   = bx1 + 400;
    float*  bx2   = by1 + 400;
    float*  by2   = bx2 + 400;
    float*  tv    = by2 + 400;
    int*       cl   = (int*)(dyn + OFFC_CL);
    unsigned*  mask = (unsigned*)(dyn + OFFC_MASK);

    __shared__ int s_n;
    __shared__ unsigned initm[NW], livem[NW], finm[NW];
    __shared__ int fi[MAXDET], warpcnt[32], warpoff[33];

    int b = blockIdx.x, t = threadIdx.x, lane = t & 31, w = t >> 5;
    unsigned lt = (1u << lane) - 1u;

    if (t == 0) { s_n = g_cnt[b]; g_cnt[b] = 0; }       // read + replay re-zero
    for (int i = t; i < NBINS; i += 1024) g_hist[b * NBINS + i] = 0u;
    __syncthreads();
    int cnt = min(s_n, KEYCAP);
    int sortn = 512;
    while (sortn < cnt) sortn <<= 1;
    // init/load only the sortn keys we'll sort
    for (int i = t; i < sortn; i += 1024)
        keys[i] = (i < cnt) ? g_keys[(size_t)b * KEYCAP + i] : 0xFFFFFFFFFFFFFFFFull;
    __syncthreads();
    bitonic(keys, sortn);

    // decode top-400
    if (t < PRE_K) {
        unsigned long long key = keys[t];
        unsigned bits = ~(unsigned)(key >> 32);
        float v = __uint_as_float(bits);
        int fidx = (int)(key & 0xFFFFFFFFull);
        if (fidx < 0 || fidx >= PP * FG) { fidx = 0; v = 0.0f; }
        int prior = fidx / FG;
        int c = fidx - prior * FG + 1;
        tv[t] = v; cl[t] = c;
        const float* L  = bbox   + ((size_t)b * PP + prior) * 4;
        const float* Pr = priors + (size_t)prior * 4;
        float px = Pr[0], py = Pr[1], pw = Pr[2], ph = Pr[3];
        float cx = L[0] * 0.1f * pw + px;
        float cy = L[1] * 0.1f * ph + py;
        float sw = expf(L[2] * 0.2f) * pw;
        float sh = expf(L[3] * 0.2f) * ph;
        float X1 = (cx - sw * 0.5f) * Wf, Y1 = (cy - sh * 0.5f) * Hf;
        float X2 = (cx + sw * 0.5f) * Wf, Y2 = (cy + sh * 0.5f) * Hf;
        bx1[t] = X1; by1[t] = Y1; bx2[t] = X2; by2[t] = Y2;
        float off = (float)c * OFFC;
        float a1 = X1 + off, a2 = Y1 + off, a3 = X2 + off, a4 = Y2 + off;
        obox4[t] = make_float4(a1, a2, a3, a4);
        ar[t] = (a3 - a1) * (a4 - a2);
    }
    __syncthreads();
    // IoU masks: float4 LDS, FMA sign test with predicated exact-div fallback
    {
        const int ITER = (NW * PRE_K + 1023) / 1024;   // 6
#pragma unroll
        for (int ii = 0; ii < ITER; ii++) {
            int idx = ii * 1024 + t;
            bool valid = (idx < NW * PRE_K);
            int vidx = valid ? idx : 0;
            int wrd = vidx / PRE_K;
            int i   = vidx - wrd * PRE_K;
            int j0  = wrd * 32;
            unsigned bst = (unsigned)max(0, min(32, i + 1 - j0));
            unsigned bmin = __reduce_min_sync(0xffffffffu, bst);
            float4 oi = obox4[i];
            float a = ar[i];
            unsigned mm = 0;
            for (unsigned bit = bmin; bit < 32; bit++) {
                int j = j0 + (int)bit;
                bool act = valid && (j > i) && (j < PRE_K);
                int js = (j < PRE_K) ? j : 0;
                float4 oj = obox4[js];
                float ltx = fmaxf(oi.x, oj.x);
                float lty = fmaxf(oi.y, oj.y);
                float rbx = fminf(oi.z, oj.z);
                float rby = fminf(oi.w, oj.w);
                float wv = fmaxf(rbx - ltx, 0.0f);
                float hv = fmaxf(rby - lty, 0.0f);
                float inter = wv * hv;
                float denom = a + ar[js] - inter + 1e-9f;
                float diff = fmaf(-NMST, denom, inter);
                bool sup = (diff > 0.0f);
                if (act && fabsf(diff) <= 3e-7f * denom)   // rare; predicated div
                    sup = (inter / denom) > NMST;
                if (act && sup) mm |= 1u << bit;
            }
            if (valid) mask[i * NW + wrd] = mm;
        }
    }
    __syncthreads();
    if (w < NW) {
        bool rm = true, nz = false;
        if (t < PRE_K) {
            rm = !(tv[t] > CONF);
            unsigned o = 0;
#pragma unroll
            for (int k = 0; k < NW; k++) o |= mask[t * NW + k];
            nz = (o != 0);
        }
        unsigned br = __ballot_sync(0xffffffffu, rm);
        unsigned bn = __ballot_sync(0xffffffffu, nz);
        if (lane == 0) { initm[w] = br; livem[w] = bn; }
    }
    __syncthreads();
    if (w == 0) {   // serial greedy walk, nz-skip (exact)
        unsigned remv = (lane < NW) ? initm[lane] : 0u;
        for (int w13 = 0; w13 < NW; w13++) {
            unsigned live = livem[w13];
            while (live) {
                int bit = __ffs(live) - 1;
                live &= live - 1;
                int i = w13 * 32 + bit;
                unsigned word = __shfl_sync(0xffffffffu, remv, w13);
                if (!((word >> bit) & 1u)) {
                    unsigned rowm = (lane < NW) ? mask[i * NW + lane] : 0u;
                    remv |= rowm;
                }
            }
        }
        if (lane < NW) finm[lane] = remv;
    }
    __syncthreads();
    bool kp = false;
    if (t < PRE_K) kp = !((finm[t >> 5] >> (t & 31)) & 1u);
    unsigned ball = __ballot_sync(0xffffffffu, kp);
    if (lane == 0) warpcnt[w] = __popc(ball);
    __syncthreads();
    if (t == 0) {
        int acc = 0;
        for (int i = 0; i < 32; i++) { warpoff[i] = acc; acc += warpcnt[i]; }
        warpoff[32] = acc;
    }
    __syncthreads();
    int nk = warpoff[32];
    if (t < PRE_K) {
        int rk = warpoff[w] + __popc(ball & lt);
        int pos = kp ? rk : nk + (t - rk);
        if (pos < MAXDET) fi[pos] = t;
    }
    __syncthreads();
    if (t < MAXDET) {
        int j = fi[t];
        bool kj = !((finm[j >> 5] >> (j & 31)) & 1u);
        int base = (b * MAXDET + t) * 4;
        out[base + 0] = bx1[j];
        out[base + 1] = by1[j];
        out[base + 2] = bx2[j];
        out[base + 3] = by2[j];
        out[BB * MAXDET * 4 + b * MAXDET + t] = (float)cl[j];
        out[BB * MAXDET * 5 + b * MAXDET + t] = kj ? tv[j] : 0.0f;
    }
}

// ------------------------------ launcher -----------------------------------
extern "C" void kernel_launch(void* const* d_in, const int* in_sizes, int n_in,
                              void* d_out, int out_size) {
    const float* logits = (const float*)d_in[0];
    const float* bbox   = (const float*)d_in[1];
    const float* priors = (const float*)d_in[2];
    float* out = (float*)d_out;

    cudaFuncSetAttribute(kC, cudaFuncAttributeMaxDynamicSharedMemorySize, DYN_C);

    int totalWarps = (BB * PP) / G;            // 40832 warps, 8 rows each
    int blocks = (totalWarps * 32 + 255) / 256;
    k1_priormax<<<blocks, 256>>>(logits);
    kAB<<<dim3(8, BB), 1024>>>(logits);
    kC<<<BB, 1024, DYN_C>>>(bbox, priors, out);
}